// round 3
// baseline (speedup 1.0000x reference)
#include <cuda_runtime.h>
#include <math.h>

#define NNODES 50000
#define DIM 128
#define MEDGE 800000
#define NWARPBLK 8
#define NODE_BLKS ((NNODES + NWARPBLK - 1) / NWARPBLK)   // 6250
#define SCAN_BS 1024
#define SCAN_NB ((NNODES + SCAN_BS - 1) / SCAN_BS)        // 49

// ------------------------- scratch (static device memory) -------------------
__device__ float g_X[NNODES * DIM];    // current node features x
__device__ float g_XN[NNODES * DIM];   // channel-normalized x (fixed per layer)
__device__ float g_S[NNODES * 32];     // per-node s vector
__device__ int   g_deg[NNODES];
__device__ int   g_tmp[NNODES];
__device__ int   g_rowoff[NNODES + 1];
__device__ int   g_cursor[NNODES + 1];
__device__ int   g_csrc[MEDGE];
__device__ int   g_bsum[64];
__device__ int   g_is64;

// ------------------------- edge index dtype handling ------------------------
__global__ void k_detect(const int* __restrict__ ei) {
    // If data is int64 (values < 50000), every odd int32 word is 0.
    __shared__ int nz;
    if (threadIdx.x == 0) nz = 0;
    __syncthreads();
    if (ei[2 * threadIdx.x + 1] != 0) atomicOr(&nz, 1);
    __syncthreads();
    if (threadIdx.x == 0) g_is64 = nz ? 0 : 1;
}

__device__ __forceinline__ int load_idx(const void* ei, long long pos, int is64) {
    if (is64) return (int)((const long long*)ei)[pos];
    return ((const int*)ei)[pos];
}

// ------------------------- CSR build ----------------------------------------
__global__ void k_zero() {
    int i = blockIdx.x * blockDim.x + threadIdx.x;
    if (i < NNODES) g_deg[i] = 0;
}

__global__ void k_hist(const void* __restrict__ ei) {
    int e = blockIdx.x * blockDim.x + threadIdx.x;
    if (e < MEDGE) {
        int t = load_idx(ei, (long long)MEDGE + e, g_is64);
        atomicAdd(&g_deg[t], 1);
    }
}

__global__ void k_scan1() {
    __shared__ int sh[SCAN_BS];
    int i = blockIdx.x * SCAN_BS + threadIdx.x;
    sh[threadIdx.x] = (i < NNODES) ? g_deg[i] : 0;
    __syncthreads();
    for (int off = 1; off < SCAN_BS; off <<= 1) {
        int t = 0;
        if ((int)threadIdx.x >= off) t = sh[threadIdx.x - off];
        __syncthreads();
        sh[threadIdx.x] += t;
        __syncthreads();
    }
    if (i < NNODES) g_tmp[i] = sh[threadIdx.x];
    if (threadIdx.x == SCAN_BS - 1) g_bsum[blockIdx.x] = sh[SCAN_BS - 1];
}

__global__ void k_scan2() {
    int run = 0;
    for (int b = 0; b < SCAN_NB; b++) {
        int t = g_bsum[b];
        g_bsum[b] = run;
        run += t;
    }
}

__global__ void k_scan3() {
    int i = blockIdx.x * blockDim.x + threadIdx.x;
    if (i < NNODES) {
        int inc = g_tmp[i] + g_bsum[i >> 10];
        g_rowoff[i + 1] = inc;
        g_cursor[i + 1] = inc;
        if (i == 0) { g_rowoff[0] = 0; g_cursor[0] = 0; }
    }
}

__global__ void k_fill(const void* __restrict__ ei) {
    int e = blockIdx.x * blockDim.x + threadIdx.x;
    if (e < MEDGE) {
        int is64 = g_is64;
        int t = load_idx(ei, (long long)MEDGE + e, is64);
        int s = load_idx(ei, e, is64);
        int pos = atomicAdd(&g_cursor[t], 1);
        g_csrc[pos] = s;
    }
}

// ------------------------- GEMM (rows x 128) @ (128 x 128) + bias -----------
__device__ __forceinline__ void gemm_body(const float* __restrict__ A,
                                          const float* __restrict__ W,
                                          const float* __restrict__ bias,
                                          float* __restrict__ C, int nrows) {
    extern __shared__ float sh[];
    float4* Ws4 = (float4*)sh;                 // 128x128 floats = 4096 f4
    float4* As4 = (float4*)(sh + DIM * DIM);   // 64x128 floats  = 2048 f4
    int tid = threadIdx.x;            // 256 threads
    int tx = tid & 31;                // column group (4 cols)
    int ty = tid >> 5;                // row group (8 rows)
    int row0 = blockIdx.x * 64;

    const float4* W4 = (const float4*)W;
#pragma unroll
    for (int i = 0; i < 16; i++) Ws4[tid + i * 256] = W4[tid + i * 256];
#pragma unroll
    for (int i = 0; i < 8; i++) {
        int idx = tid + i * 256;      // float4 index within 64x32 tile
        int r = idx >> 5;
        float4 v = make_float4(0.f, 0.f, 0.f, 0.f);
        if (row0 + r < nrows) v = ((const float4*)A)[(size_t)(row0 + r) * 32 + (idx & 31)];
        As4[idx] = v;
    }
    __syncthreads();

    float4 acc[8];
#pragma unroll
    for (int r = 0; r < 8; r++) acc[r] = make_float4(0.f, 0.f, 0.f, 0.f);

#pragma unroll
    for (int k4 = 0; k4 < 32; k4++) {
        float4 w0 = Ws4[(k4 * 4 + 0) * 32 + tx];
        float4 w1 = Ws4[(k4 * 4 + 1) * 32 + tx];
        float4 w2 = Ws4[(k4 * 4 + 2) * 32 + tx];
        float4 w3 = Ws4[(k4 * 4 + 3) * 32 + tx];
#pragma unroll
        for (int r = 0; r < 8; r++) {
            float4 a = As4[(ty * 8 + r) * 32 + k4];
            acc[r].x = fmaf(a.x, w0.x, fmaf(a.y, w1.x, fmaf(a.z, w2.x, fmaf(a.w, w3.x, acc[r].x))));
            acc[r].y = fmaf(a.x, w0.y, fmaf(a.y, w1.y, fmaf(a.z, w2.y, fmaf(a.w, w3.y, acc[r].y))));
            acc[r].z = fmaf(a.x, w0.z, fmaf(a.y, w1.z, fmaf(a.z, w2.z, fmaf(a.w, w3.z, acc[r].z))));
            acc[r].w = fmaf(a.x, w0.w, fmaf(a.y, w1.w, fmaf(a.z, w2.w, fmaf(a.w, w3.w, acc[r].w))));
        }
    }

    float4 b4 = ((const float4*)bias)[tx];
#pragma unroll
    for (int r = 0; r < 8; r++) {
        int row = row0 + ty * 8 + r;
        if (row < nrows) {
            float4 o = acc[r];
            o.x += b4.x; o.y += b4.y; o.z += b4.z; o.w += b4.w;
            ((float4*)C)[(size_t)row * 32 + tx] = o;
        }
    }
}

__global__ void k_gemm_in(const float* __restrict__ A, const float* __restrict__ W,
                          const float* __restrict__ b) {
    gemm_body(A, W, b, g_X, NNODES);
}

__global__ void k_gemm_out(const float* __restrict__ W, const float* __restrict__ b,
                           float* __restrict__ C) {
    gemm_body(g_X, W, b, C, NNODES);
}

// ------------------------- per-layer normalize + init S ---------------------
__global__ void k_norm_init() {
    int w = (blockIdx.x * blockDim.x + threadIdx.x) >> 5;
    int lane = threadIdx.x & 31;
    if (w >= NNODES) return;
    float4 v = ((const float4*)g_X)[(size_t)w * 32 + lane];
    float ss = v.x * v.x + v.y * v.y + v.z * v.z + v.w * v.w;
    ss += __shfl_xor_sync(0xffffffffu, ss, 1);
    ss += __shfl_xor_sync(0xffffffffu, ss, 2);
    ss += __shfl_xor_sync(0xffffffffu, ss, 4);
    float inv = 1.0f / fmaxf(sqrtf(ss), 1e-12f);
    v.x *= inv; v.y *= inv; v.z *= inv; v.w *= inv;
    ((float4*)g_XN)[(size_t)w * 32 + lane] = v;
    g_S[(size_t)w * 32 + lane] = v.x + v.y + v.z + v.w;
}

// ------------------------- routing iteration (warp per target node) ---------
template <bool FINAL>
__global__ void k_edge() {
    int v = (blockIdx.x * blockDim.x + threadIdx.x) >> 5;
    int lane = threadIdx.x & 31;
    if (v >= NNODES) return;

    // lane i owns elements 4i..4i+3 of the 128-float row; channel = lane>>3
    float4 s4 = ((const float4*)g_S)[(size_t)v * 8 + (lane & 7)];
    float4 acc = ((const float4*)g_XN)[(size_t)v * 32 + lane];

    int e0 = g_rowoff[v];
    int e1 = g_rowoff[v + 1];
    const float4* XN4 = (const float4*)g_XN;
    int ch = lane >> 3;

    for (int e = e0; e < e1; e++) {
        int u = __ldg(&g_csrc[e]);
        float4 g = XN4[(size_t)u * 32 + lane];
        float pd = g.x * s4.x + g.y * s4.y + g.z * s4.z + g.w * s4.w;
        pd += __shfl_xor_sync(0xffffffffu, pd, 1);
        pd += __shfl_xor_sync(0xffffffffu, pd, 2);
        pd += __shfl_xor_sync(0xffffffffu, pd, 4);
        float p0 = __shfl_sync(0xffffffffu, pd, 0);
        float p1 = __shfl_sync(0xffffffffu, pd, 8);
        float p2 = __shfl_sync(0xffffffffu, pd, 16);
        float p3 = __shfl_sync(0xffffffffu, pd, 24);
        float mx = fmaxf(fmaxf(p0, p1), fmaxf(p2, p3));
        float ex0 = __expf(p0 - mx);
        float ex1 = __expf(p1 - mx);
        float ex2 = __expf(p2 - mx);
        float ex3 = __expf(p3 - mx);
        float denom = ex0 + ex1 + ex2 + ex3;
        float ek = (ch == 0) ? ex0 : (ch == 1) ? ex1 : (ch == 2) ? ex2 : ex3;
        float wgt = __fdividef(ek, denom);
        acc.x = fmaf(wgt, g.x, acc.x);
        acc.y = fmaf(wgt, g.y, acc.y);
        acc.z = fmaf(wgt, g.z, acc.z);
        acc.w = fmaf(wgt, g.w, acc.w);
    }

    if (FINAL) {
        ((float4*)g_X)[(size_t)v * 32 + lane] = acc;
    } else {
        float ss = acc.x * acc.x + acc.y * acc.y + acc.z * acc.z + acc.w * acc.w;
        ss += __shfl_xor_sync(0xffffffffu, ss, 1);
        ss += __shfl_xor_sync(0xffffffffu, ss, 2);
        ss += __shfl_xor_sync(0xffffffffu, ss, 4);
        float inv = 1.0f / fmaxf(sqrtf(ss), 1e-12f);
        acc.x *= inv; acc.y *= inv; acc.z *= inv; acc.w *= inv;
        g_S[(size_t)v * 32 + lane] = acc.x + acc.y + acc.z + acc.w;
    }
}

// ------------------------- final copy of x into d_out -----------------------
__global__ void k_copyX(float* __restrict__ dst) {
    int i = blockIdx.x * blockDim.x + threadIdx.x;
    if (i < NNODES * DIM / 4) ((float4*)dst)[i] = ((const float4*)g_X)[i];
}

// ------------------------- launch -------------------------------------------
extern "C" void kernel_launch(void* const* d_in, const int* in_sizes, int n_in,
                              void* d_out, int out_size) {
    const float* feat  = (const float*)d_in[0];
    const void*  ei    = d_in[1];
    const float* lin_w = (const float*)d_in[2];
    const float* lin_b = (const float*)d_in[3];
    const float* mlp_w = (const float*)d_in[4];
    const float* mlp_b = (const float*)d_in[5];
    float* out = (float*)d_out;

    const int smem = (DIM * DIM + 64 * DIM) * (int)sizeof(float);  // 98304
    cudaFuncSetAttribute(k_gemm_in,  cudaFuncAttributeMaxDynamicSharedMemorySize, smem);
    cudaFuncSetAttribute(k_gemm_out, cudaFuncAttributeMaxDynamicSharedMemorySize, smem);

    // detect edge_index dtype (int32 vs int64)
    k_detect<<<1, 128>>>((const int*)ei);

    // build CSR by target (once per launch)
    k_zero<<<(NNODES + 255) / 256, 256>>>();
    k_hist<<<(MEDGE + 255) / 256, 256>>>(ei);
    k_scan1<<<SCAN_NB, SCAN_BS>>>();
    k_scan2<<<1, 1>>>();
    k_scan3<<<(NNODES + 255) / 256, 256>>>();
    k_fill<<<(MEDGE + 255) / 256, 256>>>(ei);

    // x = feat @ lin_w + lin_b
    k_gemm_in<<<(NNODES + 63) / 64, 256, smem>>>(feat, lin_w, lin_b);

    for (int layer = 0; layer < 2; layer++) {
        k_norm_init<<<NODE_BLKS, NWARPBLK * 32>>>();
        k_edge<false><<<NODE_BLKS, NWARPBLK * 32>>>();
        k_edge<false><<<NODE_BLKS, NWARPBLK * 32>>>();
        k_edge<true><<<NODE_BLKS, NWARPBLK * 32>>>();
    }

    // out = x @ mlp_w + mlp_b ; then x itself
    k_gemm_out<<<(NNODES + 63) / 64, 256, smem>>>(mlp_w, mlp_b, out);
    k_copyX<<<(NNODES * DIM / 4 + 1023) / 1024, 1024>>>(out + (size_t)NNODES * DIM);
}

// round 4
// speedup vs baseline: 1.0603x; 1.0603x over previous
#include <cuda_runtime.h>
#include <cuda_fp16.h>
#include <math.h>

#define NNODES 50000
#define DIM 128
#define MEDGE 800000
#define NWARPBLK 8
#define NODE_BLKS ((NNODES + NWARPBLK - 1) / NWARPBLK)   // 6250
#define SCAN_BS 1024
#define SCAN_NB ((NNODES + SCAN_BS - 1) / SCAN_BS)        // 49

// ------------------------- scratch (static device memory) -------------------
__device__ float g_X[NNODES * DIM];     // current node features x (fp32)
__device__ float g_XN[NNODES * DIM];    // normalized x, fp32 (self term only)
__device__ uint2 g_XNH[NNODES * 32];    // normalized x, fp16 (edge gathers)
__device__ float g_S[NNODES * 32];      // per-node s vector
__device__ int   g_deg[NNODES];
__device__ int   g_tmp[NNODES];
__device__ int   g_rowoff[NNODES + 1];
__device__ int   g_cursor[NNODES + 1];
__device__ int   g_csrc[MEDGE];
__device__ int   g_bsum[64];
__device__ int   g_is64;

// ------------------------- edge index dtype handling ------------------------
__global__ void k_detect(const int* __restrict__ ei) {
    __shared__ int nz;
    if (threadIdx.x == 0) nz = 0;
    __syncthreads();
    if (ei[2 * threadIdx.x + 1] != 0) atomicOr(&nz, 1);
    __syncthreads();
    if (threadIdx.x == 0) g_is64 = nz ? 0 : 1;
}

__device__ __forceinline__ int load_idx(const void* ei, long long pos, int is64) {
    if (is64) return (int)((const long long*)ei)[pos];
    return ((const int*)ei)[pos];
}

// ------------------------- CSR build ----------------------------------------
__global__ void k_zero() {
    int i = blockIdx.x * blockDim.x + threadIdx.x;
    if (i < NNODES) g_deg[i] = 0;
}

__global__ void k_hist(const void* __restrict__ ei) {
    int e = blockIdx.x * blockDim.x + threadIdx.x;
    if (e < MEDGE) {
        int t = load_idx(ei, (long long)MEDGE + e, g_is64);
        atomicAdd(&g_deg[t], 1);
    }
}

__global__ void k_scan1() {
    __shared__ int sh[SCAN_BS];
    int i = blockIdx.x * SCAN_BS + threadIdx.x;
    sh[threadIdx.x] = (i < NNODES) ? g_deg[i] : 0;
    __syncthreads();
    for (int off = 1; off < SCAN_BS; off <<= 1) {
        int t = 0;
        if ((int)threadIdx.x >= off) t = sh[threadIdx.x - off];
        __syncthreads();
        sh[threadIdx.x] += t;
        __syncthreads();
    }
    if (i < NNODES) g_tmp[i] = sh[threadIdx.x];
    if (threadIdx.x == SCAN_BS - 1) g_bsum[blockIdx.x] = sh[SCAN_BS - 1];
}

__global__ void k_scan2() {
    int run = 0;
    for (int b = 0; b < SCAN_NB; b++) {
        int t = g_bsum[b];
        g_bsum[b] = run;
        run += t;
    }
}

__global__ void k_scan3() {
    int i = blockIdx.x * blockDim.x + threadIdx.x;
    if (i < NNODES) {
        int inc = g_tmp[i] + g_bsum[i >> 10];
        g_rowoff[i + 1] = inc;
        g_cursor[i + 1] = inc;
        if (i == 0) { g_rowoff[0] = 0; g_cursor[0] = 0; }
    }
}

__global__ void k_fill(const void* __restrict__ ei) {
    int e = blockIdx.x * blockDim.x + threadIdx.x;
    if (e < MEDGE) {
        int is64 = g_is64;
        int t = load_idx(ei, (long long)MEDGE + e, is64);
        int s = load_idx(ei, e, is64);
        int pos = atomicAdd(&g_cursor[t], 1);
        g_csrc[pos] = s;
    }
}

// ------------------------- GEMM (rows x 128) @ (128 x 128) + bias -----------
__device__ __forceinline__ void gemm_body(const float* __restrict__ A,
                                          const float* __restrict__ W,
                                          const float* __restrict__ bias,
                                          float* __restrict__ C, int nrows) {
    extern __shared__ float sh[];
    float4* Ws4 = (float4*)sh;                 // 128x128 floats
    float4* As4 = (float4*)(sh + DIM * DIM);   // 64x128 floats
    int tid = threadIdx.x;            // 256 threads
    int tx = tid & 31;                // column group (4 cols)
    int ty = tid >> 5;                // row group (8 rows)
    int row0 = blockIdx.x * 64;

    const float4* W4 = (const float4*)W;
#pragma unroll
    for (int i = 0; i < 16; i++) Ws4[tid + i * 256] = W4[tid + i * 256];
#pragma unroll
    for (int i = 0; i < 8; i++) {
        int idx = tid + i * 256;
        int r = idx >> 5;
        float4 v = make_float4(0.f, 0.f, 0.f, 0.f);
        if (row0 + r < nrows) v = ((const float4*)A)[(size_t)(row0 + r) * 32 + (idx & 31)];
        As4[idx] = v;
    }
    __syncthreads();

    float4 acc[8];
#pragma unroll
    for (int r = 0; r < 8; r++) acc[r] = make_float4(0.f, 0.f, 0.f, 0.f);

#pragma unroll
    for (int k4 = 0; k4 < 32; k4++) {
        float4 w0 = Ws4[(k4 * 4 + 0) * 32 + tx];
        float4 w1 = Ws4[(k4 * 4 + 1) * 32 + tx];
        float4 w2 = Ws4[(k4 * 4 + 2) * 32 + tx];
        float4 w3 = Ws4[(k4 * 4 + 3) * 32 + tx];
#pragma unroll
        for (int r = 0; r < 8; r++) {
            float4 a = As4[(ty * 8 + r) * 32 + k4];
            acc[r].x = fmaf(a.x, w0.x, fmaf(a.y, w1.x, fmaf(a.z, w2.x, fmaf(a.w, w3.x, acc[r].x))));
            acc[r].y = fmaf(a.x, w0.y, fmaf(a.y, w1.y, fmaf(a.z, w2.y, fmaf(a.w, w3.y, acc[r].y))));
            acc[r].z = fmaf(a.x, w0.z, fmaf(a.y, w1.z, fmaf(a.z, w2.z, fmaf(a.w, w3.z, acc[r].z))));
            acc[r].w = fmaf(a.x, w0.w, fmaf(a.y, w1.w, fmaf(a.z, w2.w, fmaf(a.w, w3.w, acc[r].w))));
        }
    }

    float4 b4 = ((const float4*)bias)[tx];
#pragma unroll
    for (int r = 0; r < 8; r++) {
        int row = row0 + ty * 8 + r;
        if (row < nrows) {
            float4 o = acc[r];
            o.x += b4.x; o.y += b4.y; o.z += b4.z; o.w += b4.w;
            ((float4*)C)[(size_t)row * 32 + tx] = o;
        }
    }
}

__global__ void k_gemm_in(const float* __restrict__ A, const float* __restrict__ W,
                          const float* __restrict__ b) {
    gemm_body(A, W, b, g_X, NNODES);
}

__global__ void k_gemm_out(const float* __restrict__ W, const float* __restrict__ b,
                           float* __restrict__ C) {
    gemm_body(g_X, W, b, C, NNODES);
}

// ------------------------- per-layer normalize + init S ---------------------
__global__ void k_norm_init() {
    int w = (blockIdx.x * blockDim.x + threadIdx.x) >> 5;
    int lane = threadIdx.x & 31;
    if (w >= NNODES) return;
    float4 v = ((const float4*)g_X)[(size_t)w * 32 + lane];
    float ss = v.x * v.x + v.y * v.y + v.z * v.z + v.w * v.w;
    ss += __shfl_xor_sync(0xffffffffu, ss, 1);
    ss += __shfl_xor_sync(0xffffffffu, ss, 2);
    ss += __shfl_xor_sync(0xffffffffu, ss, 4);
    float inv = 1.0f / fmaxf(sqrtf(ss), 1e-12f);
    v.x *= inv; v.y *= inv; v.z *= inv; v.w *= inv;
    ((float4*)g_XN)[(size_t)w * 32 + lane] = v;
    // fp16 copy for the edge gathers
    __half2 h0 = __floats2half2_rn(v.x, v.y);
    __half2 h1 = __floats2half2_rn(v.z, v.w);
    uint2 pk;
    pk.x = *reinterpret_cast<unsigned int*>(&h0);
    pk.y = *reinterpret_cast<unsigned int*>(&h1);
    g_XNH[(size_t)w * 32 + lane] = pk;
    g_S[(size_t)w * 32 + lane] = v.x + v.y + v.z + v.w;
}

// ------------------------- routing iteration (warp per target node) ---------
template <bool FINAL>
__global__ void k_edge() {
    int v = (blockIdx.x * blockDim.x + threadIdx.x) >> 5;
    int lane = threadIdx.x & 31;
    if (v >= NNODES) return;

    // lane i owns elements 4i..4i+3 of the 128-float row; channel = lane>>3
    float4 s4 = ((const float4*)g_S)[(size_t)v * 8 + (lane & 7)];
    float4 acc = ((const float4*)g_XN)[(size_t)v * 32 + lane];

    int e0 = g_rowoff[v];
    int e1 = g_rowoff[v + 1];
    const uint2* XNH = g_XNH;
    const unsigned full = 0xffffffffu;

    for (int base = e0; base < e1; base += 32) {
        int nch = e1 - base; if (nch > 32) nch = 32;
        int myu = 0;
        if (lane < nch) myu = __ldg(&g_csrc[base + lane]);
        for (int j = 0; j < nch; j++) {
            int u = __shfl_sync(full, myu, j);
            uint2 raw = __ldg(&XNH[(size_t)u * 32 + lane]);
            __half2 h0 = *reinterpret_cast<__half2*>(&raw.x);
            __half2 h1 = *reinterpret_cast<__half2*>(&raw.y);
            float2 f0 = __half22float2(h0);
            float2 f1 = __half22float2(h1);
            float pd = f0.x * s4.x + f0.y * s4.y + f1.x * s4.z + f1.y * s4.w;
            // reduce within 8-lane channel group
            pd += __shfl_xor_sync(full, pd, 1);
            pd += __shfl_xor_sync(full, pd, 2);
            pd += __shfl_xor_sync(full, pd, 4);
            // butterfly exchange of the 4 channel logits (own = pd)
            float pb = __shfl_xor_sync(full, pd, 8);
            float pc = __shfl_xor_sync(full, pd, 16);
            float pe = __shfl_xor_sync(full, pb, 16);   // xor 24
            float mx = fmaxf(fmaxf(pd, pb), fmaxf(pc, pe));
            float exa = __expf(pd - mx);
            float exb = __expf(pb - mx);
            float exc = __expf(pc - mx);
            float exd = __expf(pe - mx);
            float wgt = __fdividef(exa, exa + exb + exc + exd);
            acc.x = fmaf(wgt, f0.x, acc.x);
            acc.y = fmaf(wgt, f0.y, acc.y);
            acc.z = fmaf(wgt, f1.x, acc.z);
            acc.w = fmaf(wgt, f1.y, acc.w);
        }
    }

    if (FINAL) {
        ((float4*)g_X)[(size_t)v * 32 + lane] = acc;
    } else {
        float ss = acc.x * acc.x + acc.y * acc.y + acc.z * acc.z + acc.w * acc.w;
        ss += __shfl_xor_sync(full, ss, 1);
        ss += __shfl_xor_sync(full, ss, 2);
        ss += __shfl_xor_sync(full, ss, 4);
        float inv = 1.0f / fmaxf(sqrtf(ss), 1e-12f);
        acc.x *= inv; acc.y *= inv; acc.z *= inv; acc.w *= inv;
        g_S[(size_t)v * 32 + lane] = acc.x + acc.y + acc.z + acc.w;
    }
}

// ------------------------- final copy of x into d_out -----------------------
__global__ void k_copyX(float* __restrict__ dst) {
    int i = blockIdx.x * blockDim.x + threadIdx.x;
    if (i < NNODES * DIM / 4) ((float4*)dst)[i] = ((const float4*)g_X)[i];
}

// ------------------------- launch -------------------------------------------
extern "C" void kernel_launch(void* const* d_in, const int* in_sizes, int n_in,
                              void* d_out, int out_size) {
    const float* feat  = (const float*)d_in[0];
    const void*  ei    = d_in[1];
    const float* lin_w = (const float*)d_in[2];
    const float* lin_b = (const float*)d_in[3];
    const float* mlp_w = (const float*)d_in[4];
    const float* mlp_b = (const float*)d_in[5];
    float* out = (float*)d_out;

    const int smem = (DIM * DIM + 64 * DIM) * (int)sizeof(float);  // 98304
    cudaFuncSetAttribute(k_gemm_in,  cudaFuncAttributeMaxDynamicSharedMemorySize, smem);
    cudaFuncSetAttribute(k_gemm_out, cudaFuncAttributeMaxDynamicSharedMemorySize, smem);

    // detect edge_index dtype (int32 vs int64)
    k_detect<<<1, 128>>>((const int*)ei);

    // build CSR by target (once per launch)
    k_zero<<<(NNODES + 255) / 256, 256>>>();
    k_hist<<<(MEDGE + 255) / 256, 256>>>(ei);
    k_scan1<<<SCAN_NB, SCAN_BS>>>();
    k_scan2<<<1, 1>>>();
    k_scan3<<<(NNODES + 255) / 256, 256>>>();
    k_fill<<<(MEDGE + 255) / 256, 256>>>(ei);

    // x = feat @ lin_w + lin_b
    k_gemm_in<<<(NNODES + 63) / 64, 256, smem>>>(feat, lin_w, lin_b);

    for (int layer = 0; layer < 2; layer++) {
        k_norm_init<<<NODE_BLKS, NWARPBLK * 32>>>();
        k_edge<false><<<NODE_BLKS, NWARPBLK * 32>>>();
        k_edge<false><<<NODE_BLKS, NWARPBLK * 32>>>();
        k_edge<true><<<NODE_BLKS, NWARPBLK * 32>>>();
    }

    // out = x @ mlp_w + mlp_b ; then x itself
    k_gemm_out<<<(NNODES + 63) / 64, 256, smem>>>(mlp_w, mlp_b, out);
    k_copyX<<<(NNODES * DIM / 4 + 1023) / 1024, 1024>>>(out + (size_t)NNODES * DIM);
}

// round 5
// speedup vs baseline: 1.2058x; 1.1372x over previous
#include <cuda_runtime.h>
#include <cuda_fp16.h>
#include <math.h>

#define NNODES 50000
#define DIM 128
#define MEDGE 800000
#define NWARPBLK 8
#define NODE_BLKS ((NNODES + NWARPBLK - 1) / NWARPBLK)   // 6250
#define SCAN_BS 1024
#define SCAN_NB ((NNODES + SCAN_BS - 1) / SCAN_BS)        // 49

// ------------------------- scratch (static device memory) -------------------
__device__ float g_X[NNODES * DIM];     // current node features x (fp32)
__device__ float g_XN[NNODES * DIM];    // normalized x, fp32 (self term only)
__device__ uint2 g_XNH[NNODES * 32];    // normalized x, fp16 (edge gathers)
__device__ float g_S[NNODES * 32];      // per-node s vector
__device__ int   g_deg[NNODES];
__device__ int   g_tmp[NNODES];
__device__ int   g_rowoff[NNODES + 1];
__device__ int   g_cursor[NNODES + 1];
__device__ int   g_csrc[MEDGE];
__device__ int   g_bsum[64];
__device__ int   g_is64;

__device__ __forceinline__ float ex2(float x) {
    float r;
    asm("ex2.approx.f32 %0, %1;" : "=f"(r) : "f"(x));
    return r;
}

// ------------------------- edge index dtype handling ------------------------
__global__ void k_detect(const int* __restrict__ ei) {
    __shared__ int nz;
    if (threadIdx.x == 0) nz = 0;
    __syncthreads();
    if (ei[2 * threadIdx.x + 1] != 0) atomicOr(&nz, 1);
    __syncthreads();
    if (threadIdx.x == 0) g_is64 = nz ? 0 : 1;
}

__device__ __forceinline__ int load_idx(const void* ei, long long pos, int is64) {
    if (is64) return (int)((const long long*)ei)[pos];
    return ((const int*)ei)[pos];
}

// ------------------------- CSR build ----------------------------------------
__global__ void k_zero() {
    int i = blockIdx.x * blockDim.x + threadIdx.x;
    if (i < NNODES) g_deg[i] = 0;
}

__global__ void k_hist(const void* __restrict__ ei) {
    int e = blockIdx.x * blockDim.x + threadIdx.x;
    if (e < MEDGE) {
        int t = load_idx(ei, (long long)MEDGE + e, g_is64);
        atomicAdd(&g_deg[t], 1);
    }
}

__global__ void k_scan1() {
    __shared__ int sh[SCAN_BS];
    int i = blockIdx.x * SCAN_BS + threadIdx.x;
    sh[threadIdx.x] = (i < NNODES) ? g_deg[i] : 0;
    __syncthreads();
    for (int off = 1; off < SCAN_BS; off <<= 1) {
        int t = 0;
        if ((int)threadIdx.x >= off) t = sh[threadIdx.x - off];
        __syncthreads();
        sh[threadIdx.x] += t;
        __syncthreads();
    }
    if (i < NNODES) g_tmp[i] = sh[threadIdx.x];
    if (threadIdx.x == SCAN_BS - 1) g_bsum[blockIdx.x] = sh[SCAN_BS - 1];
}

__global__ void k_scan2() {
    int run = 0;
    for (int b = 0; b < SCAN_NB; b++) {
        int t = g_bsum[b];
        g_bsum[b] = run;
        run += t;
    }
}

__global__ void k_scan3() {
    int i = blockIdx.x * blockDim.x + threadIdx.x;
    if (i < NNODES) {
        int inc = g_tmp[i] + g_bsum[i >> 10];
        g_rowoff[i + 1] = inc;
        g_cursor[i + 1] = inc;
        if (i == 0) { g_rowoff[0] = 0; g_cursor[0] = 0; }
    }
}

__global__ void k_fill(const void* __restrict__ ei) {
    int e = blockIdx.x * blockDim.x + threadIdx.x;
    if (e < MEDGE) {
        int is64 = g_is64;
        int t = load_idx(ei, (long long)MEDGE + e, is64);
        int s = load_idx(ei, e, is64);
        int pos = atomicAdd(&g_cursor[t], 1);
        g_csrc[pos] = s;
    }
}

// ------------------------- GEMM (rows x 128) @ (128 x 128) + bias -----------
__device__ __forceinline__ void gemm_body(const float* __restrict__ A,
                                          const float* __restrict__ W,
                                          const float* __restrict__ bias,
                                          float* __restrict__ C, int nrows) {
    extern __shared__ float sh[];
    float4* Ws4 = (float4*)sh;                 // 128x128 floats
    float4* As4 = (float4*)(sh + DIM * DIM);   // 64x128 floats
    int tid = threadIdx.x;            // 256 threads
    int tx = tid & 31;                // column group (4 cols)
    int ty = tid >> 5;                // row group (8 rows)
    int row0 = blockIdx.x * 64;

    const float4* W4 = (const float4*)W;
#pragma unroll
    for (int i = 0; i < 16; i++) Ws4[tid + i * 256] = W4[tid + i * 256];
#pragma unroll
    for (int i = 0; i < 8; i++) {
        int idx = tid + i * 256;
        int r = idx >> 5;
        float4 v = make_float4(0.f, 0.f, 0.f, 0.f);
        if (row0 + r < nrows) v = ((const float4*)A)[(size_t)(row0 + r) * 32 + (idx & 31)];
        As4[idx] = v;
    }
    __syncthreads();

    float4 acc[8];
#pragma unroll
    for (int r = 0; r < 8; r++) acc[r] = make_float4(0.f, 0.f, 0.f, 0.f);

#pragma unroll
    for (int k4 = 0; k4 < 32; k4++) {
        float4 w0 = Ws4[(k4 * 4 + 0) * 32 + tx];
        float4 w1 = Ws4[(k4 * 4 + 1) * 32 + tx];
        float4 w2 = Ws4[(k4 * 4 + 2) * 32 + tx];
        float4 w3 = Ws4[(k4 * 4 + 3) * 32 + tx];
#pragma unroll
        for (int r = 0; r < 8; r++) {
            float4 a = As4[(ty * 8 + r) * 32 + k4];
            acc[r].x = fmaf(a.x, w0.x, fmaf(a.y, w1.x, fmaf(a.z, w2.x, fmaf(a.w, w3.x, acc[r].x))));
            acc[r].y = fmaf(a.x, w0.y, fmaf(a.y, w1.y, fmaf(a.z, w2.y, fmaf(a.w, w3.y, acc[r].y))));
            acc[r].z = fmaf(a.x, w0.z, fmaf(a.y, w1.z, fmaf(a.z, w2.z, fmaf(a.w, w3.z, acc[r].z))));
            acc[r].w = fmaf(a.x, w0.w, fmaf(a.y, w1.w, fmaf(a.z, w2.w, fmaf(a.w, w3.w, acc[r].w))));
        }
    }

    float4 b4 = ((const float4*)bias)[tx];
#pragma unroll
    for (int r = 0; r < 8; r++) {
        int row = row0 + ty * 8 + r;
        if (row < nrows) {
            float4 o = acc[r];
            o.x += b4.x; o.y += b4.y; o.z += b4.z; o.w += b4.w;
            ((float4*)C)[(size_t)row * 32 + tx] = o;
        }
    }
}

__global__ void k_gemm_in(const float* __restrict__ A, const float* __restrict__ W,
                          const float* __restrict__ b) {
    gemm_body(A, W, b, g_X, NNODES);
}

__global__ void k_gemm_out(const float* __restrict__ W, const float* __restrict__ b,
                           float* __restrict__ C) {
    gemm_body(g_X, W, b, C, NNODES);
}

// ------------------------- per-layer normalize + init S ---------------------
__global__ void k_norm_init() {
    int w = (blockIdx.x * blockDim.x + threadIdx.x) >> 5;
    int lane = threadIdx.x & 31;
    if (w >= NNODES) return;
    float4 v = ((const float4*)g_X)[(size_t)w * 32 + lane];
    float ss = v.x * v.x + v.y * v.y + v.z * v.z + v.w * v.w;
    ss += __shfl_xor_sync(0xffffffffu, ss, 1);
    ss += __shfl_xor_sync(0xffffffffu, ss, 2);
    ss += __shfl_xor_sync(0xffffffffu, ss, 4);
    float inv = 1.0f / fmaxf(sqrtf(ss), 1e-12f);
    v.x *= inv; v.y *= inv; v.z *= inv; v.w *= inv;
    ((float4*)g_XN)[(size_t)w * 32 + lane] = v;
    // fp16 copy for the edge gathers
    __half2 h0 = __floats2half2_rn(v.x, v.y);
    __half2 h1 = __floats2half2_rn(v.z, v.w);
    uint2 pk;
    pk.x = *reinterpret_cast<unsigned int*>(&h0);
    pk.y = *reinterpret_cast<unsigned int*>(&h1);
    g_XNH[(size_t)w * 32 + lane] = pk;
    g_S[(size_t)w * 32 + lane] = v.x + v.y + v.z + v.w;
}

// ------------------------- routing iteration -------------------------------
// One warp per target node, 4 edges processed simultaneously (8 lanes/edge).
// Lane = grp*8 + sub; lane owns elements [16*sub, 16*sub+16) of the 128-row.
// Channel of those elements = sub>>1; a-offset within channel = (sub&1)*16.
template <bool FINAL>
__global__ void k_edge() {
    int v = (blockIdx.x * blockDim.x + threadIdx.x) >> 5;
    int lane = threadIdx.x & 31;
    if (v >= NNODES) return;
    int grp = lane >> 3;          // edge slot 0..3
    int sub = lane & 7;           // lane within edge group
    int half = sub & 1;           // which 16-element half of the channel
    const unsigned full = 0xffffffffu;
    const float LOG2E = 1.4426950408889634f;

    // s values for this lane's a-range, pre-scaled by log2(e) (TAU=1)
    float sv[16];
    {
        const float4* srow = (const float4*)(g_S + (size_t)v * 32 + half * 16);
#pragma unroll
        for (int q = 0; q < 4; q++) {
            float4 t = srow[q];
            sv[4 * q + 0] = t.x * LOG2E;
            sv[4 * q + 1] = t.y * LOG2E;
            sv[4 * q + 2] = t.z * LOG2E;
            sv[4 * q + 3] = t.w * LOG2E;
        }
    }

    // accumulator: group 0 seeds with the self term x_norm[v]
    float acc[16];
    if (grp == 0) {
        const float4* xnrow = (const float4*)(g_XN + (size_t)v * DIM + sub * 16);
#pragma unroll
        for (int q = 0; q < 4; q++) {
            float4 t = xnrow[q];
            acc[4 * q + 0] = t.x; acc[4 * q + 1] = t.y;
            acc[4 * q + 2] = t.z; acc[4 * q + 3] = t.w;
        }
    } else {
#pragma unroll
        for (int j = 0; j < 16; j++) acc[j] = 0.f;
    }

    int e0 = g_rowoff[v];
    int e1 = g_rowoff[v + 1];
    int niter = (e1 - e0 + 3) >> 2;
    const uint4* XNH4 = (const uint4*)g_XNH;   // 16 uint4 per 128-fp16 row

    for (int it = 0; it < niter; it++) {
        int e = e0 + it * 4 + grp;
        bool valid = (e < e1);
        int u = 0;
        if (sub == 0 && valid) u = __ldg(&g_csrc[e]);
        u = __shfl_sync(full, u, grp << 3);

        uint4 r0 = __ldg(&XNH4[(size_t)u * 16 + sub * 2]);
        uint4 r1 = __ldg(&XNH4[(size_t)u * 16 + sub * 2 + 1]);
        float f[16];
        {
            const __half2* hp = (const __half2*)&r0;
#pragma unroll
            for (int q = 0; q < 4; q++) {
                float2 t = __half22float2(hp[q]);
                f[2 * q] = t.x; f[2 * q + 1] = t.y;
            }
            const __half2* hq = (const __half2*)&r1;
#pragma unroll
            for (int q = 0; q < 4; q++) {
                float2 t = __half22float2(hq[q]);
                f[8 + 2 * q] = t.x; f[8 + 2 * q + 1] = t.y;
            }
        }

        float pd = 0.f;
#pragma unroll
        for (int j = 0; j < 16; j++) pd = fmaf(f[j], sv[j], pd);
        pd += __shfl_xor_sync(full, pd, 1);        // full channel logit (×log2e)
        float pb = __shfl_xor_sync(full, pd, 2);   // channel ^1
        float pc = __shfl_xor_sync(full, pd, 4);   // channel ^2
        float pe = __shfl_xor_sync(full, pb, 4);   // channel ^3
        float mx = fmaxf(fmaxf(pd, pb), fmaxf(pc, pe));
        float ea = ex2(pd - mx);
        float eb = ex2(pb - mx);
        float ec = ex2(pc - mx);
        float ed = ex2(pe - mx);
        float wgt = valid ? __fdividef(ea, ea + eb + ec + ed) : 0.f;
#pragma unroll
        for (int j = 0; j < 16; j++) acc[j] = fmaf(wgt, f[j], acc[j]);
    }

    // merge the 4 edge-group accumulators
#pragma unroll
    for (int j = 0; j < 16; j++) {
        acc[j] += __shfl_xor_sync(full, acc[j], 8);
        acc[j] += __shfl_xor_sync(full, acc[j], 16);
    }

    if (grp == 0) {
        if (FINAL) {
            float4* o = (float4*)(g_X + (size_t)v * DIM + sub * 16);
#pragma unroll
            for (int q = 0; q < 4; q++)
                o[q] = make_float4(acc[4 * q], acc[4 * q + 1], acc[4 * q + 2], acc[4 * q + 3]);
        } else {
            float ss = 0.f;
#pragma unroll
            for (int j = 0; j < 16; j++) ss = fmaf(acc[j], acc[j], ss);
            ss += __shfl_xor_sync(0xffu, ss, 1);   // other half of this channel
            float inv = 1.0f / fmaxf(sqrtf(ss), 1e-12f);
            float4 sout;
            sout.x = (acc[0] + acc[1] + acc[2] + acc[3]) * inv;
            sout.y = (acc[4] + acc[5] + acc[6] + acc[7]) * inv;
            sout.z = (acc[8] + acc[9] + acc[10] + acc[11]) * inv;
            sout.w = (acc[12] + acc[13] + acc[14] + acc[15]) * inv;
            ((float4*)(g_S + (size_t)v * 32))[sub] = sout;
        }
    }
}

// ------------------------- final copy of x into d_out -----------------------
__global__ void k_copyX(float* __restrict__ dst) {
    int i = blockIdx.x * blockDim.x + threadIdx.x;
    if (i < NNODES * DIM / 4) ((float4*)dst)[i] = ((const float4*)g_X)[i];
}

// ------------------------- launch -------------------------------------------
extern "C" void kernel_launch(void* const* d_in, const int* in_sizes, int n_in,
                              void* d_out, int out_size) {
    const float* feat  = (const float*)d_in[0];
    const void*  ei    = d_in[1];
    const float* lin_w = (const float*)d_in[2];
    const float* lin_b = (const float*)d_in[3];
    const float* mlp_w = (const float*)d_in[4];
    const float* mlp_b = (const float*)d_in[5];
    float* out = (float*)d_out;

    const int smem = (DIM * DIM + 64 * DIM) * (int)sizeof(float);  // 98304
    cudaFuncSetAttribute(k_gemm_in,  cudaFuncAttributeMaxDynamicSharedMemorySize, smem);
    cudaFuncSetAttribute(k_gemm_out, cudaFuncAttributeMaxDynamicSharedMemorySize, smem);

    // detect edge_index dtype (int32 vs int64)
    k_detect<<<1, 128>>>((const int*)ei);

    // build CSR by target (once per launch)
    k_zero<<<(NNODES + 255) / 256, 256>>>();
    k_hist<<<(MEDGE + 255) / 256, 256>>>(ei);
    k_scan1<<<SCAN_NB, SCAN_BS>>>();
    k_scan2<<<1, 1>>>();
    k_scan3<<<(NNODES + 255) / 256, 256>>>();
    k_fill<<<(MEDGE + 255) / 256, 256>>>(ei);

    // x = feat @ lin_w + lin_b
    k_gemm_in<<<(NNODES + 63) / 64, 256, smem>>>(feat, lin_w, lin_b);

    for (int layer = 0; layer < 2; layer++) {
        k_norm_init<<<NODE_BLKS, NWARPBLK * 32>>>();
        k_edge<false><<<NODE_BLKS, NWARPBLK * 32>>>();
        k_edge<false><<<NODE_BLKS, NWARPBLK * 32>>>();
        k_edge<true><<<NODE_BLKS, NWARPBLK * 32>>>();
    }

    // out = x @ mlp_w + mlp_b ; then x itself
    k_gemm_out<<<(NNODES + 63) / 64, 256, smem>>>(mlp_w, mlp_b, out);
    k_copyX<<<(NNODES * DIM / 4 + 1023) / 1024, 1024>>>(out + (size_t)NNODES * DIM);
}

// round 6
// speedup vs baseline: 1.4221x; 1.1794x over previous
#include <cuda_runtime.h>
#include <cuda_fp16.h>
#include <math.h>

#define NNODES 50000
#define DIM 128
#define MEDGE 800000
#define NWARPBLK 8
#define NODE_BLKS ((NNODES + NWARPBLK - 1) / NWARPBLK)   // 6250
#define SCAN_BS 1024
#define SCAN_NB ((NNODES + SCAN_BS - 1) / SCAN_BS)        // 49

// ------------------------- scratch (static device memory) -------------------
__device__ float g_X[NNODES * DIM];     // current node features x (fp32)
__device__ float g_XN[NNODES * DIM];    // normalized x, fp32 (self term only)
__device__ uint2 g_XNH[NNODES * 32];    // normalized x, fp16 (edge gathers)
__device__ float g_S[NNODES * 32];      // per-node s vector
__device__ int   g_deg[NNODES];
__device__ int   g_tmp[NNODES];
__device__ int   g_rowoff[NNODES + 1];
__device__ int   g_cursor[NNODES + 1];
__device__ int   g_csrc[MEDGE];
__device__ int   g_bsum[64];
__device__ int   g_is64;

__device__ __forceinline__ float ex2(float x) {
    float r;
    asm("ex2.approx.f32 %0, %1;" : "=f"(r) : "f"(x));
    return r;
}

// ------------------------- edge index dtype handling ------------------------
__global__ void k_detect(const int* __restrict__ ei) {
    __shared__ int nz;
    if (threadIdx.x == 0) nz = 0;
    __syncthreads();
    if (ei[2 * threadIdx.x + 1] != 0) atomicOr(&nz, 1);
    __syncthreads();
    if (threadIdx.x == 0) g_is64 = nz ? 0 : 1;
}

__device__ __forceinline__ int load_idx(const void* ei, long long pos, int is64) {
    if (is64) return (int)((const long long*)ei)[pos];
    return ((const int*)ei)[pos];
}

// ------------------------- CSR build ----------------------------------------
__global__ void k_zero() {
    int i = blockIdx.x * blockDim.x + threadIdx.x;
    if (i < NNODES) g_deg[i] = 0;
}

__global__ void k_hist(const void* __restrict__ ei) {
    int e = blockIdx.x * blockDim.x + threadIdx.x;
    if (e < MEDGE) {
        int t = load_idx(ei, (long long)MEDGE + e, g_is64);
        atomicAdd(&g_deg[t], 1);
    }
}

__global__ void k_scan1() {
    __shared__ int wsum[32];
    const unsigned full = 0xffffffffu;
    int i = blockIdx.x * SCAN_BS + threadIdx.x;
    int lane = threadIdx.x & 31;
    int wid = threadIdx.x >> 5;
    int s = (i < NNODES) ? g_deg[i] : 0;
#pragma unroll
    for (int o = 1; o < 32; o <<= 1) {
        int t = __shfl_up_sync(full, s, o);
        if (lane >= o) s += t;
    }
    if (lane == 31) wsum[wid] = s;
    __syncthreads();
    if (wid == 0) {
        int w = wsum[lane];
#pragma unroll
        for (int o = 1; o < 32; o <<= 1) {
            int t = __shfl_up_sync(full, w, o);
            if (lane >= o) w += t;
        }
        wsum[lane] = w;
    }
    __syncthreads();
    int total = s + (wid ? wsum[wid - 1] : 0);
    if (i < NNODES) g_tmp[i] = total;
    if (threadIdx.x == SCAN_BS - 1) g_bsum[blockIdx.x] = total;
}

// scan of block sums fused into the add-offsets pass
__global__ void k_scan3() {
    __shared__ int bx[SCAN_NB];
    if (threadIdx.x < SCAN_NB) bx[threadIdx.x] = g_bsum[threadIdx.x];
    __syncthreads();
    if (threadIdx.x == 0) {
        int run = 0;
#pragma unroll
        for (int b = 0; b < SCAN_NB; b++) { int t = bx[b]; bx[b] = run; run += t; }
    }
    __syncthreads();
    int i = blockIdx.x * blockDim.x + threadIdx.x;
    if (i < NNODES) {
        int inc = g_tmp[i] + bx[i >> 10];
        g_rowoff[i + 1] = inc;
        g_cursor[i + 1] = inc;
        if (i == 0) { g_rowoff[0] = 0; g_cursor[0] = 0; }
    }
}

__global__ void k_fill(const void* __restrict__ ei) {
    int e = blockIdx.x * blockDim.x + threadIdx.x;
    if (e < MEDGE) {
        int is64 = g_is64;
        int t = load_idx(ei, (long long)MEDGE + e, is64);
        int s = load_idx(ei, e, is64);
        int pos = atomicAdd(&g_cursor[t], 1);
        g_csrc[pos] = s;
    }
}

// ------------------------- GEMM (rows x 128) @ (128 x 128) + bias -----------
template <bool COPY_A>
__device__ __forceinline__ void gemm_body(const float* __restrict__ A,
                                          const float* __restrict__ W,
                                          const float* __restrict__ bias,
                                          float* __restrict__ C,
                                          float* __restrict__ Acopy, int nrows) {
    extern __shared__ float sh[];
    float4* Ws4 = (float4*)sh;                 // 128x128 floats
    float4* As4 = (float4*)(sh + DIM * DIM);   // 64x128 floats
    int tid = threadIdx.x;            // 256 threads
    int tx = tid & 31;                // column group (4 cols)
    int ty = tid >> 5;                // row group (8 rows)
    int row0 = blockIdx.x * 64;

    const float4* W4 = (const float4*)W;
#pragma unroll
    for (int i = 0; i < 16; i++) Ws4[tid + i * 256] = W4[tid + i * 256];
#pragma unroll
    for (int i = 0; i < 8; i++) {
        int idx = tid + i * 256;
        int r = idx >> 5;
        float4 v = make_float4(0.f, 0.f, 0.f, 0.f);
        if (row0 + r < nrows) v = ((const float4*)A)[(size_t)(row0 + r) * 32 + (idx & 31)];
        As4[idx] = v;
    }
    __syncthreads();

    float4 acc[8];
#pragma unroll
    for (int r = 0; r < 8; r++) acc[r] = make_float4(0.f, 0.f, 0.f, 0.f);

#pragma unroll
    for (int k4 = 0; k4 < 32; k4++) {
        float4 w0 = Ws4[(k4 * 4 + 0) * 32 + tx];
        float4 w1 = Ws4[(k4 * 4 + 1) * 32 + tx];
        float4 w2 = Ws4[(k4 * 4 + 2) * 32 + tx];
        float4 w3 = Ws4[(k4 * 4 + 3) * 32 + tx];
#pragma unroll
        for (int r = 0; r < 8; r++) {
            float4 a = As4[(ty * 8 + r) * 32 + k4];
            acc[r].x = fmaf(a.x, w0.x, fmaf(a.y, w1.x, fmaf(a.z, w2.x, fmaf(a.w, w3.x, acc[r].x))));
            acc[r].y = fmaf(a.x, w0.y, fmaf(a.y, w1.y, fmaf(a.z, w2.y, fmaf(a.w, w3.y, acc[r].y))));
            acc[r].z = fmaf(a.x, w0.z, fmaf(a.y, w1.z, fmaf(a.z, w2.z, fmaf(a.w, w3.z, acc[r].z))));
            acc[r].w = fmaf(a.x, w0.w, fmaf(a.y, w1.w, fmaf(a.z, w2.w, fmaf(a.w, w3.w, acc[r].w))));
        }
    }

    float4 b4 = ((const float4*)bias)[tx];
#pragma unroll
    for (int r = 0; r < 8; r++) {
        int row = row0 + ty * 8 + r;
        if (row < nrows) {
            float4 o = acc[r];
            o.x += b4.x; o.y += b4.y; o.z += b4.z; o.w += b4.w;
            ((float4*)C)[(size_t)row * 32 + tx] = o;
        }
    }

    if (COPY_A) {
        // A tile (x rows) is still in smem — stream it to Acopy
#pragma unroll
        for (int i = 0; i < 8; i++) {
            int idx = tid + i * 256;
            int r = idx >> 5;
            if (row0 + r < nrows)
                ((float4*)Acopy)[(size_t)(row0 + r) * 32 + (idx & 31)] = As4[idx];
        }
    }
}

__global__ void k_gemm_in(const float* __restrict__ A, const float* __restrict__ W,
                          const float* __restrict__ b) {
    gemm_body<false>(A, W, b, g_X, nullptr, NNODES);
}

__global__ void k_gemm_out(const float* __restrict__ W, const float* __restrict__ b,
                           float* __restrict__ C, float* __restrict__ Xout) {
    gemm_body<true>(g_X, W, b, C, Xout, NNODES);
}

// ------------------------- per-layer normalize + init S ---------------------
__global__ void k_norm_init() {
    int w = (blockIdx.x * blockDim.x + threadIdx.x) >> 5;
    int lane = threadIdx.x & 31;
    if (w >= NNODES) return;
    float4 v = ((const float4*)g_X)[(size_t)w * 32 + lane];
    float ss = v.x * v.x + v.y * v.y + v.z * v.z + v.w * v.w;
    ss += __shfl_xor_sync(0xffffffffu, ss, 1);
    ss += __shfl_xor_sync(0xffffffffu, ss, 2);
    ss += __shfl_xor_sync(0xffffffffu, ss, 4);
    float inv = 1.0f / fmaxf(sqrtf(ss), 1e-12f);
    v.x *= inv; v.y *= inv; v.z *= inv; v.w *= inv;
    ((float4*)g_XN)[(size_t)w * 32 + lane] = v;
    __half2 h0 = __floats2half2_rn(v.x, v.y);
    __half2 h1 = __floats2half2_rn(v.z, v.w);
    uint2 pk;
    pk.x = *reinterpret_cast<unsigned int*>(&h0);
    pk.y = *reinterpret_cast<unsigned int*>(&h1);
    g_XNH[(size_t)w * 32 + lane] = pk;
    g_S[(size_t)w * 32 + lane] = v.x + v.y + v.z + v.w;
}

// ------------------------- routing iteration -------------------------------
// One warp per target node, 4 edges per iteration (8 lanes/edge),
// software-pipelined: next iteration's index + feature loads issue before
// this iteration's compute chain.
template <bool FINAL>
__global__ void k_edge() {
    int v = (blockIdx.x * blockDim.x + threadIdx.x) >> 5;
    int lane = threadIdx.x & 31;
    if (v >= NNODES) return;
    int grp = lane >> 3;          // edge slot 0..3
    int sub = lane & 7;           // lane within edge group
    int half = sub & 1;           // which 16-element half of the channel
    const unsigned full = 0xffffffffu;
    const float LOG2E = 1.4426950408889634f;

    // s values for this lane's a-range, pre-scaled by log2(e) (TAU=1)
    float sv[16];
    {
        const float4* srow = (const float4*)(g_S + (size_t)v * 32 + half * 16);
#pragma unroll
        for (int q = 0; q < 4; q++) {
            float4 t = srow[q];
            sv[4 * q + 0] = t.x * LOG2E;
            sv[4 * q + 1] = t.y * LOG2E;
            sv[4 * q + 2] = t.z * LOG2E;
            sv[4 * q + 3] = t.w * LOG2E;
        }
    }

    // accumulator: group 0 seeds with the self term x_norm[v]
    float acc[16];
    if (grp == 0) {
        const float4* xnrow = (const float4*)(g_XN + (size_t)v * DIM + sub * 16);
#pragma unroll
        for (int q = 0; q < 4; q++) {
            float4 t = xnrow[q];
            acc[4 * q + 0] = t.x; acc[4 * q + 1] = t.y;
            acc[4 * q + 2] = t.z; acc[4 * q + 3] = t.w;
        }
    } else {
#pragma unroll
        for (int j = 0; j < 16; j++) acc[j] = 0.f;
    }

    int e0 = g_rowoff[v];
    int e1 = g_rowoff[v + 1];
    int niter = (e1 - e0 + 3) >> 2;
    const uint4* XNH4 = (const uint4*)g_XNH;   // 16 uint4 per 128-fp16 row

    // prefetch iteration 0
    int u = 0;
    {
        int e = e0 + grp;
        if (sub == 0 && e < e1) u = __ldg(&g_csrc[e]);
        u = __shfl_sync(full, u, grp << 3);
    }
    uint4 r0 = __ldg(&XNH4[(size_t)u * 16 + sub * 2]);
    uint4 r1 = __ldg(&XNH4[(size_t)u * 16 + sub * 2 + 1]);

    for (int it = 0; it < niter; it++) {
        // ---- prefetch it+1 (overlaps the compute chain below) ----
        int en = e0 + (it + 1) * 4 + grp;
        int un = 0;
        if (sub == 0 && en < e1) un = __ldg(&g_csrc[en]);
        un = __shfl_sync(full, un, grp << 3);
        uint4 n0 = __ldg(&XNH4[(size_t)un * 16 + sub * 2]);
        uint4 n1 = __ldg(&XNH4[(size_t)un * 16 + sub * 2 + 1]);

        bool valid = (e0 + it * 4 + grp) < e1;

        // ---- decode current ----
        float f[16];
        {
            const __half2* hp = (const __half2*)&r0;
#pragma unroll
            for (int q = 0; q < 4; q++) {
                float2 t = __half22float2(hp[q]);
                f[2 * q] = t.x; f[2 * q + 1] = t.y;
            }
            const __half2* hq = (const __half2*)&r1;
#pragma unroll
            for (int q = 0; q < 4; q++) {
                float2 t = __half22float2(hq[q]);
                f[8 + 2 * q] = t.x; f[8 + 2 * q + 1] = t.y;
            }
        }

        float pd = 0.f;
#pragma unroll
        for (int j = 0; j < 16; j++) pd = fmaf(f[j], sv[j], pd);
        pd += __shfl_xor_sync(full, pd, 1);        // full channel logit (×log2e)
        float pb = __shfl_xor_sync(full, pd, 2);   // channel ^1
        float pc = __shfl_xor_sync(full, pd, 4);   // channel ^2
        float pe = __shfl_xor_sync(full, pb, 4);   // channel ^3
        // |logit*log2e| <= ~5.8 (s from normalized data) -> no max-subtract
        float ea = ex2(pd);
        float eb = ex2(pb);
        float ec = ex2(pc);
        float ed = ex2(pe);
        float wgt = valid ? __fdividef(ea, ea + eb + ec + ed) : 0.f;
#pragma unroll
        for (int j = 0; j < 16; j++) acc[j] = fmaf(wgt, f[j], acc[j]);

        r0 = n0; r1 = n1;
    }

    // merge the 4 edge-group accumulators
#pragma unroll
    for (int j = 0; j < 16; j++) {
        acc[j] += __shfl_xor_sync(full, acc[j], 8);
        acc[j] += __shfl_xor_sync(full, acc[j], 16);
    }

    if (grp == 0) {
        if (FINAL) {
            float4* o = (float4*)(g_X + (size_t)v * DIM + sub * 16);
#pragma unroll
            for (int q = 0; q < 4; q++)
                o[q] = make_float4(acc[4 * q], acc[4 * q + 1], acc[4 * q + 2], acc[4 * q + 3]);
        } else {
            float ss = 0.f;
#pragma unroll
            for (int j = 0; j < 16; j++) ss = fmaf(acc[j], acc[j], ss);
            ss += __shfl_xor_sync(0xffu, ss, 1);   // other half of this channel
            float inv = 1.0f / fmaxf(sqrtf(ss), 1e-12f);
            float4 sout;
            sout.x = (acc[0] + acc[1] + acc[2] + acc[3]) * inv;
            sout.y = (acc[4] + acc[5] + acc[6] + acc[7]) * inv;
            sout.z = (acc[8] + acc[9] + acc[10] + acc[11]) * inv;
            sout.w = (acc[12] + acc[13] + acc[14] + acc[15]) * inv;
            ((float4*)(g_S + (size_t)v * 32))[sub] = sout;
        }
    }
}

// ------------------------- launch -------------------------------------------
extern "C" void kernel_launch(void* const* d_in, const int* in_sizes, int n_in,
                              void* d_out, int out_size) {
    const float* feat  = (const float*)d_in[0];
    const void*  ei    = d_in[1];
    const float* lin_w = (const float*)d_in[2];
    const float* lin_b = (const float*)d_in[3];
    const float* mlp_w = (const float*)d_in[4];
    const float* mlp_b = (const float*)d_in[5];
    float* out = (float*)d_out;

    const int smem = (DIM * DIM + 64 * DIM) * (int)sizeof(float);  // 98304
    cudaFuncSetAttribute(k_gemm_in,  cudaFuncAttributeMaxDynamicSharedMemorySize, smem);
    cudaFuncSetAttribute(k_gemm_out, cudaFuncAttributeMaxDynamicSharedMemorySize, smem);

    // 1: detect edge_index dtype (int32 vs int64)
    k_detect<<<1, 128>>>((const int*)ei);
    // 2-3: CSR histogram
    k_zero<<<(NNODES + 255) / 256, 256>>>();
    k_hist<<<(MEDGE + 255) / 256, 256>>>(ei);
    // 4: x = feat @ lin_w + lin_b   (positioned here so ncu -s captures it)
    k_gemm_in<<<(NNODES + 63) / 64, 256, smem>>>(feat, lin_w, lin_b);
    // 5-7: finish CSR
    k_scan1<<<SCAN_NB, SCAN_BS>>>();
    k_scan3<<<(NNODES + 255) / 256, 256>>>();
    k_fill<<<(MEDGE + 255) / 256, 256>>>(ei);

    for (int layer = 0; layer < 2; layer++) {
        k_norm_init<<<NODE_BLKS, NWARPBLK * 32>>>();
        k_edge<false><<<NODE_BLKS, NWARPBLK * 32>>>();
        k_edge<false><<<NODE_BLKS, NWARPBLK * 32>>>();
        k_edge<true><<<NODE_BLKS, NWARPBLK * 32>>>();
    }

    // out = x @ mlp_w + mlp_b ; epilogue also streams x into out[NNODES*DIM..]
    k_gemm_out<<<(NNODES + 63) / 64, 256, smem>>>(mlp_w, mlp_b, out,
                                                  out + (size_t)NNODES * DIM);
}